// round 1
// baseline (speedup 1.0000x reference)
#include <cuda_runtime.h>

// LNCC loss: 9x9x9 box-window local NCC over (B=2, 160^3) fp32 volumes,
// replicate padding (== clamped indices), output = -mean(ncc), scalar fp32.
//
// Fully fused single-pass kernel:
//   - block tile: 32 (w) x 16 (h) outputs, slides over a D-chunk of 32
//   - per D-plane: load raw x,y tile with halo -> 9-tap W sums of the 5
//     products -> 9-tap H sums -> update per-thread running D sums via a
//     9-deep circular buffer in smem -> emit ncc, accumulate
//   - raw data read exactly once per block (plus halo amplification);
//     no intermediate global tensors at all.

#define BB   2
#define DD   160
#define HH   160
#define WW   160
#define RAD  4
#define WT   32
#define HT   16
#define DCH  32
#define NCHUNK (DD / DCH)          // 5
#define RAWW (WT + 2 * RAD)        // 40
#define RAWH (HT + 2 * RAD)        // 24
#define NTHREADS (WT * HT)         // 512

// smem floats: raw x + raw y + wsum(5 fields) + circ(9 x 5 x HT x WT)
#define SM_RAW   (RAWH * RAWW)               // 960
#define SM_WS    (5 * RAWH * WT)             // 3840
#define SM_CIRC  (9 * 5 * HT * WT)           // 23040
#define SMEM_FLOATS (2 * SM_RAW + SM_WS + SM_CIRC)   // 28800
#define SMEM_BYTES  (SMEM_FLOATS * 4)                // 115200

__device__ double g_acc;

__global__ void zero_acc_kernel() { g_acc = 0.0; }

__global__ void finalize_kernel(float* out) {
    out[0] = (float)(-g_acc * (1.0 / ((double)BB * DD * HH * WW)));
}

__device__ __forceinline__ int iclamp(int v, int hi) {
    return min(max(v, 0), hi);
}

extern __shared__ float smem[];

__global__ __launch_bounds__(NTHREADS, 2)
void lncc_kernel(const float* __restrict__ x, const float* __restrict__ y) {
    float* xr   = smem;                  // [RAWH][RAWW]
    float* yr   = xr + SM_RAW;           // [RAWH][RAWW]
    float* ws   = yr + SM_RAW;           // [5][RAWH][WT]
    float* circ = ws + SM_WS;            // [9][5][HT][WT]

    const int tx  = threadIdx.x;         // 0..31  (w within tile)
    const int ty  = threadIdx.y;         // 0..15  (h within tile)
    const int tid = ty * WT + tx;

    const int w0    = blockIdx.x * WT;
    const int h0    = blockIdx.y * HT;
    const int b     = blockIdx.z / NCHUNK;
    const int chunk = blockIdx.z % NCHUNK;
    const int d0    = chunk * DCH;

    const float* xb = x + (size_t)b * DD * HH * WW;
    const float* yb = y + (size_t)b * DD * HH * WW;

    // zero circular buffer
    for (int e = tid; e < SM_CIRC; e += NTHREADS) circ[e] = 0.0f;

    float run0 = 0.f, run1 = 0.f, run2 = 0.f, run3 = 0.f, run4 = 0.f;
    float acc = 0.f;

    // planes j = d0-4 .. d0+DCH+3; output d = j-4 once j >= d0+4.
    for (int step = 0; step < DCH + 2 * RAD; ++step) {
        const int j  = d0 - RAD + step;
        const int gd = iclamp(j, DD - 1);
        const float* xp = xb + (size_t)gd * HH * WW;
        const float* yp = yb + (size_t)gd * HH * WW;

        __syncthreads();  // protect raw/ws from previous iteration readers

        // ---- load raw tile with halo (clamped h, w) ----
        #pragma unroll
        for (int e = tid; e < SM_RAW; e += NTHREADS) {
            int row = e / RAWW;
            int col = e - row * RAWW;
            int gh = iclamp(h0 - RAD + row, HH - 1);
            int gw = iclamp(w0 - RAD + col, WW - 1);
            int off = gh * WW + gw;
            xr[e] = __ldg(xp + off);
            yr[e] = __ldg(yp + off);
        }
        __syncthreads();

        // ---- stage A: 9-tap W sums of the 5 products, for all 24 rows ----
        for (int rr = ty; rr < RAWH; rr += HT) {
            float sx = 0.f, sy = 0.f, sxx = 0.f, syy = 0.f, sxy = 0.f;
            const float* xrow = xr + rr * RAWW + tx;
            const float* yrow = yr + rr * RAWW + tx;
            #pragma unroll
            for (int k = 0; k < 9; ++k) {
                float xv = xrow[k];
                float yv = yrow[k];
                sx += xv;
                sy += yv;
                sxx = fmaf(xv, xv, sxx);
                syy = fmaf(yv, yv, syy);
                sxy = fmaf(xv, yv, sxy);
            }
            int base = rr * WT + tx;
            ws[0 * RAWH * WT + base] = sx;
            ws[1 * RAWH * WT + base] = sy;
            ws[2 * RAWH * WT + base] = sxx;
            ws[3 * RAWH * WT + base] = syy;
            ws[4 * RAWH * WT + base] = sxy;
        }
        __syncthreads();

        // ---- stage B: 9-tap H sums + D sliding window ----
        float nv[5];
        #pragma unroll
        for (int f = 0; f < 5; ++f) {
            const float* col = ws + (f * RAWH + ty) * WT + tx;
            float s = 0.f;
            #pragma unroll
            for (int k = 0; k < 9; ++k) s += col[k * WT];
            nv[f] = s;
        }

        const int slot = step % 9;
        float* cbase = circ + ((slot * 5) * HT + ty) * WT + tx;
        {
            float o0 = cbase[0 * HT * WT];
            float o1 = cbase[1 * HT * WT];
            float o2 = cbase[2 * HT * WT];
            float o3 = cbase[3 * HT * WT];
            float o4 = cbase[4 * HT * WT];
            run0 += nv[0] - o0;  cbase[0 * HT * WT] = nv[0];
            run1 += nv[1] - o1;  cbase[1 * HT * WT] = nv[1];
            run2 += nv[2] - o2;  cbase[2 * HT * WT] = nv[2];
            run3 += nv[3] - o3;  cbase[3 * HT * WT] = nv[3];
            run4 += nv[4] - o4;  cbase[4 * HT * WT] = nv[4];
        }

        // ---- emit output for d = j - 4 ----
        if (j >= d0 + RAD) {
            const float invn = 1.0f / 729.0f;
            float xm = run0 * invn;
            float ym = run1 * invn;
            float cross = fmaf(-xm, ym, run4 * invn);
            float vx    = fmaf(-xm, xm, run2 * invn);
            float vy    = fmaf(-ym, ym, run3 * invn);
            float ncc = (cross * cross) / fmaf(vx, vy, 1e-5f);
            acc += ncc;
        }
    }

    // ---- block reduction -> global double accumulator ----
    __syncthreads();
    #pragma unroll
    for (int o = 16; o > 0; o >>= 1)
        acc += __shfl_down_sync(0xffffffffu, acc, o);
    const int warp = tid >> 5;
    const int lane = tid & 31;
    if (lane == 0) xr[warp] = acc;   // reuse smem
    __syncthreads();
    if (warp == 0) {
        float v = (lane < NTHREADS / 32) ? xr[lane] : 0.0f;
        #pragma unroll
        for (int o = 8; o > 0; o >>= 1)
            v += __shfl_down_sync(0xffffffffu, v, o);
        if (lane == 0) atomicAdd(&g_acc, (double)v);
    }
}

extern "C" void kernel_launch(void* const* d_in, const int* in_sizes, int n_in,
                              void* d_out, int out_size) {
    const float* x = (const float*)d_in[0];
    const float* y = (const float*)d_in[1];
    float* out = (float*)d_out;

    cudaFuncSetAttribute(lncc_kernel,
                         cudaFuncAttributeMaxDynamicSharedMemorySize,
                         SMEM_BYTES);

    zero_acc_kernel<<<1, 1>>>();
    dim3 grid(WW / WT, HH / HT, BB * NCHUNK);   // (5, 10, 10) = 500 blocks
    dim3 block(WT, HT);                          // 512 threads
    lncc_kernel<<<grid, block, SMEM_BYTES>>>(x, y);
    finalize_kernel<<<1, 1>>>(out);
}

// round 2
// speedup vs baseline: 1.1578x; 1.1578x over previous
#include <cuda_runtime.h>
#include <cuda_fp16.h>

// LNCC loss, two-pass separable:
//   pass1: per (b,d) plane: 9-tap W sums of {x,y,x2,y2,xy} (packed f32x2 math),
//          9-tap H sums via per-thread register sliding window, -> fp16 scratch
//   pass2: 9-tap D sliding window per (h,w) column + NCC + global reduction.

#define BB 2
#define DD 160
#define HH 160
#define WW 160
#define VOLSZ (DD*HH*WW)
#define VOL2  (BB*VOLSZ)

#define NH 2
#define HS (HH/NH)          // 80
#define ROWS (HS + 8)       // 88

#define ND 2
#define DS (DD/ND)          // 80
#define STEPS (DS + 8)      // 88

__device__ __half2 g_scrA[VOL2];   // (Sx,  Sy)
__device__ __half2 g_scrB[VOL2];   // (Sxx, Syy)
__device__ __half  g_scrC[VOL2];   // Sxy
__device__ double  g_acc;

__global__ void zero_acc_kernel() { g_acc = 0.0; }

__global__ void finalize_kernel(float* out) {
    out[0] = (float)(-g_acc * (1.0 / (double)VOL2));
}

// ---- packed f32x2 helpers (sm_100+) ----
__device__ __forceinline__ unsigned long long pk2(float a, float b) {
    unsigned long long r;
    asm("mov.b64 %0, {%1, %2};" : "=l"(r) : "f"(a), "f"(b));
    return r;
}
__device__ __forceinline__ void upk2(unsigned long long v, float& a, float& b) {
    asm("mov.b64 {%0, %1}, %2;" : "=f"(a), "=f"(b) : "l"(v));
}
#define ADD2(d, a, b) asm("add.rn.f32x2 %0, %1, %2;" : "=l"(d) : "l"(a), "l"(b))
#define FMA2(d, a, b, c) asm("fma.rn.f32x2 %0, %1, %2, %3;" : "=l"(d) : "l"(a), "l"(b), "l"(c))

__device__ __forceinline__ int iclamp(int v, int hi) { return min(max(v, 0), hi); }

// ================= pass 1: W sums (direct) + H sums (sliding) =================
__global__ __launch_bounds__(160)
void lncc_pass1(const float* __restrict__ x, const float* __restrict__ y) {
    __shared__ float2 buf[2][WW + 8];     // interleaved (x,y) row, with W halo

    const int tx    = threadIdx.x;        // 0..159 (w)
    const int strip = blockIdx.x;
    const int d     = blockIdx.y;
    const int b     = blockIdx.z;
    const int hs0   = strip * HS;

    const float* xp = x + ((size_t)b * DD + d) * (HH * WW);
    const float* yp = y + ((size_t)b * DD + d) * (HH * WW);

    // prologue: load row ih=0
    {
        int gh = iclamp(hs0 - 4, HH - 1);
        const float* xr = xp + gh * WW;
        const float* yr = yp + gh * WW;
        int gw = iclamp(tx - 4, WW - 1);
        buf[0][tx] = make_float2(__ldg(xr + gw), __ldg(yr + gw));
        if (tx < 8) {
            int gw2 = min(156 + tx, WW - 1);
            buf[0][WW + tx] = make_float2(__ldg(xr + gw2), __ldg(yr + gw2));
        }
    }
    __syncthreads();

    float ha[9], hb[9], hc[9], hd[9], he[9];
    #pragma unroll
    for (int k = 0; k < 9; ++k) { ha[k]=0.f; hb[k]=0.f; hc[k]=0.f; hd[k]=0.f; he[k]=0.f; }
    float r0=0.f, r1=0.f, r2=0.f, r3=0.f, r4=0.f;

    const size_t obase = ((size_t)b * DD + d) * (HH * WW) + tx;

    for (int grp = 0; grp < 10; ++grp) {
        #pragma unroll
        for (int k = 0; k < 9; ++k) {
            const int ih = grp * 9 + k;
            if (ih < ROWS) {           // uniform across block
                const float2* cur = buf[ih & 1];

                // prefetch next row into the other buffer
                if (ih + 1 < ROWS) {
                    float2* nxt = buf[(ih + 1) & 1];
                    int gh = iclamp(hs0 - 4 + ih + 1, HH - 1);
                    const float* xr = xp + gh * WW;
                    const float* yr = yp + gh * WW;
                    int gw = iclamp(tx - 4, WW - 1);
                    nxt[tx] = make_float2(__ldg(xr + gw), __ldg(yr + gw));
                    if (tx < 8) {
                        int gw2 = min(156 + tx, WW - 1);
                        nxt[WW + tx] = make_float2(__ldg(xr + gw2), __ldg(yr + gw2));
                    }
                }

                // 9-tap W sums with packed f32x2 math
                unsigned long long s01 = 0ull, s23 = 0ull;  // (0.f,0.f)
                float sxy = 0.f;
                #pragma unroll
                for (int t = 0; t < 9; ++t) {
                    float2 p = cur[tx + t];
                    unsigned long long pp = pk2(p.x, p.y);
                    ADD2(s01, s01, pp);
                    FMA2(s23, pp, pp, s23);
                    sxy = fmaf(p.x, p.y, sxy);
                }
                float nsx, nsy, nsxx, nsyy;
                upk2(s01, nsx, nsy);
                upk2(s23, nsxx, nsyy);

                // H sliding window (register history, static slot k)
                r0 += nsx  - ha[k]; ha[k] = nsx;
                r1 += nsy  - hb[k]; hb[k] = nsy;
                r2 += nsxx - hc[k]; hc[k] = nsxx;
                r3 += nsyy - hd[k]; hd[k] = nsyy;
                r4 += sxy  - he[k]; he[k] = sxy;

                if (ih >= 8) {
                    size_t o = obase + (size_t)(hs0 + ih - 8) * WW;
                    g_scrA[o] = __floats2half2_rn(r0, r1);
                    g_scrB[o] = __floats2half2_rn(r2, r3);
                    g_scrC[o] = __float2half_rn(r4);
                }
                __syncthreads();
            }
        }
    }
}

// ================= pass 2: D sliding + NCC + reduction =================
__global__ __launch_bounds__(160)
void lncc_pass2() {
    const int tx = threadIdx.x;          // w
    const int h  = blockIdx.x;
    const int dc = blockIdx.y;
    const int b  = blockIdx.z;
    const int d0 = dc * DS;

    float ha[9], hb[9], hc[9], hd[9], he[9];
    #pragma unroll
    for (int k = 0; k < 9; ++k) { ha[k]=0.f; hb[k]=0.f; hc[k]=0.f; hd[k]=0.f; he[k]=0.f; }
    float r0=0.f, r1=0.f, r2=0.f, r3=0.f, r4=0.f;
    float acc = 0.f;

    const size_t base = ((size_t)b * DD) * (HH * WW) + (size_t)h * WW + tx;
    const float invn = 1.0f / 729.0f;

    for (int grp = 0; grp < 10; ++grp) {
        #pragma unroll
        for (int k = 0; k < 9; ++k) {
            const int jd = grp * 9 + k;
            if (jd < STEPS) {
                int gd = iclamp(d0 - 4 + jd, DD - 1);
                size_t idx = base + (size_t)gd * (HH * WW);
                float2 a = __half22float2(g_scrA[idx]);
                float2 q = __half22float2(g_scrB[idx]);
                float  c = __half2float(g_scrC[idx]);

                r0 += a.x - ha[k]; ha[k] = a.x;
                r1 += a.y - hb[k]; hb[k] = a.y;
                r2 += q.x - hc[k]; hc[k] = q.x;
                r3 += q.y - hd[k]; hd[k] = q.y;
                r4 += c   - he[k]; he[k] = c;

                if (jd >= 8) {
                    float xm = r0 * invn;
                    float ym = r1 * invn;
                    float cross = fmaf(-xm, ym, r4 * invn);
                    float vx    = fmaf(-xm, xm, r2 * invn);
                    float vy    = fmaf(-ym, ym, r3 * invn);
                    acc += __fdividef(cross * cross, fmaf(vx, vy, 1e-5f));
                }
            }
        }
    }

    // block reduce (5 warps) -> double atomic
    __shared__ float red[5];
    #pragma unroll
    for (int o = 16; o > 0; o >>= 1)
        acc += __shfl_down_sync(0xffffffffu, acc, o);
    const int warp = tx >> 5;
    const int lane = tx & 31;
    if (lane == 0) red[warp] = acc;
    __syncthreads();
    if (warp == 0) {
        float v = (lane < 5) ? red[lane] : 0.0f;
        #pragma unroll
        for (int o = 4; o > 0; o >>= 1)
            v += __shfl_down_sync(0xffffffffu, v, o);
        if (lane == 0) atomicAdd(&g_acc, (double)v);
    }
}

extern "C" void kernel_launch(void* const* d_in, const int* in_sizes, int n_in,
                              void* d_out, int out_size) {
    const float* x = (const float*)d_in[0];
    const float* y = (const float*)d_in[1];
    float* out = (float*)d_out;

    zero_acc_kernel<<<1, 1>>>();

    dim3 g1(NH, DD, BB);          // 2 x 160 x 2 = 640 blocks
    lncc_pass1<<<g1, 160>>>(x, y);

    dim3 g2(HH, ND, BB);          // 160 x 2 x 2 = 640 blocks
    lncc_pass2<<<g2, 160>>>();

    finalize_kernel<<<1, 1>>>(out);
}